// round 12
// baseline (speedup 1.0000x reference)
#include <cuda_runtime.h>
#include <math.h>

// Problem constants
#define N_   256
#define T_   1000
#define NO_  10
#define NS_  10
#define HID_ 64
#define G3_  192   // 3*HID
#define D_   20    // NO+NS

// Scratch: xproj [N*T,192], hidden states [N,T,64], global double accumulator.
__device__ float  g_xp[(size_t)N_ * T_ * G3_];
__device__ float  g_h[(size_t)N_ * T_ * HID_];
__device__ double g_acc;

__global__ void k_zero() { g_acc = 0.0; }
__global__ void k_pad() { }   // no-op: keeps k_gru at ncu capture slot (idx 3)

// ---- packed f32x2 helpers ----
#define FMA2(d, a, b, c) \
    asm("fma.rn.f32x2 %0, %1, %2, %3;" : "=l"(d) : "l"(a), "l"(b), "l"(c))
#define ADD2(d, a, b) \
    asm("add.rn.f32x2 %0, %1, %2;" : "=l"(d) : "l"(a), "l"(b))
#define PACK2(d, lo, hi) \
    asm("mov.b64 %0, {%1, %2};" : "=l"(d) : "f"(lo), "f"(hi))
#define UNPACK2(lo, hi, s) \
    asm("mov.b64 {%0, %1}, %2;" : "=f"(lo), "=f"(hi) : "l"(s))

// ---- fast activations via MUFU.TANH (sm_75+) ----
__device__ __forceinline__ float tanh_fast(float x) {
    float y;
    asm("tanh.approx.f32 %0, %1;" : "=f"(y) : "f"(x));
    return y;
}
__device__ __forceinline__ float sigmoid_fast(float x) {
    return fmaf(tanh_fast(0.5f * x), 0.5f, 0.5f);
}
__device__ __forceinline__ float softplusf_(float x) {
    float ax = fabsf(x);
    return fmaxf(x, 0.0f) + log1pf(__expf(-ax));
}

// ---------------------------------------------------------------------------
// Kernel 0: precompute input projections xp[nt][192] = concat(y,xhat)@Wi + bi
// ---------------------------------------------------------------------------
__global__ void __launch_bounds__(G3_) k_xp(
    const float* __restrict__ Yi, const float* __restrict__ Xh,
    const float* __restrict__ Wi, const float* __restrict__ bi)
{
    __shared__ float xs[16][D_];
    const int j = threadIdx.x;
    const int nt0 = blockIdx.x * 16;
    for (int i = j; i < 16 * D_; i += G3_) {
        int r = i / D_, d = i - r * D_;
        int nt = nt0 + r;
        xs[r][d] = (d < NO_) ? Yi[(size_t)nt * NO_ + d]
                             : Xh[(size_t)nt * NS_ + (d - NO_)];
    }
    float w[D_];
#pragma unroll
    for (int d = 0; d < D_; d++) w[d] = Wi[d * G3_ + j];
    const float b = bi[j];
    __syncthreads();
#pragma unroll
    for (int r = 0; r < 16; r++) {
        float a = b;
#pragma unroll
        for (int d = 0; d < D_; d++) a = fmaf(xs[r][d], w[d], a);
        g_xp[(size_t)(nt0 + r) * G3_ + j] = a;
    }
}

// ---------------------------------------------------------------------------
// Kernel 1: persistent GRU, TWO samples per thread (ILP over the recurrence).
// Grid 128, block 64. Thread u owns unit u of samples 2b and 2b+1; the
// weight registers (96 f32x2 pairs) are SHARED between both samples.
// Two independent dot-chain sets interleave in one warp -> latency hiding
// without inter-thread traffic. ONE barrier per step; MUFU.TANH.
// ---------------------------------------------------------------------------
struct XPre { float r, z, n; };

__device__ __forceinline__ XPre ld_xp(const float* base, int u) {
    XPre o;
    o.r = __ldg(base + u);
    o.z = __ldg(base + HID_ + u);
    o.n = __ldg(base + 2 * HID_ + u);
    return o;
}

// one GRU gate-evaluation for one sample given packed dot partials
__device__ __forceinline__ void gru_finish(
    unsigned long long sr, unsigned long long sz, unsigned long long sn,
    float bhR, float bhZ, float bhN, XPre xp, float& hreg)
{
    float rl, rh, zl, zh, nl, nh;
    UNPACK2(rl, rh, sr);
    UNPACK2(zl, zh, sz);
    UNPACK2(nl, nh, sn);
    float r  = sigmoid_fast(xp.r + bhR + rl + rh);
    float z  = sigmoid_fast(xp.z + bhZ + zl + zh);
    float nn = tanh_fast(xp.n + r * (bhN + nl + nh));
    hreg = fmaf(z, hreg - nn, nn);       // (1-z)*nn + z*h
}

__global__ void __launch_bounds__(HID_, 1) k_gru(
    const float* __restrict__ Wh, const float* __restrict__ bh)
{
    __shared__ __align__(16) float sh_hA[2][HID_];
    __shared__ __align__(16) float sh_hB[2][HID_];

    const int u  = threadIdx.x;          // unit id, 0..63
    const int nA = blockIdx.x * 2;
    const int nB = nA + 1;

    // weights for columns u (r), 64+u (z), 128+u (n): 96 packed pairs (shared)
    unsigned long long wr2[HID_ / 2], wz2[HID_ / 2], wn2[HID_ / 2];
#pragma unroll
    for (int k = 0; k < HID_ / 2; k++) {
        float a, b;
        a = Wh[(2 * k) * G3_ + u];             b = Wh[(2 * k + 1) * G3_ + u];
        PACK2(wr2[k], a, b);
        a = Wh[(2 * k) * G3_ + HID_ + u];      b = Wh[(2 * k + 1) * G3_ + HID_ + u];
        PACK2(wz2[k], a, b);
        a = Wh[(2 * k) * G3_ + 2 * HID_ + u];  b = Wh[(2 * k + 1) * G3_ + 2 * HID_ + u];
        PACK2(wn2[k], a, b);
    }
    const float bhR = bh[u], bhZ = bh[HID_ + u], bhN = bh[2 * HID_ + u];

    const float* xptA = g_xp + (size_t)nA * T_ * G3_;
    const float* xptB = g_xp + (size_t)nB * T_ * G3_;
    float*       hbA  = g_h  + (size_t)nA * T_ * HID_;
    float*       hbB  = g_h  + (size_t)nB * T_ * HID_;

    float hA = 0.0f, hB = 0.0f;
    sh_hA[0][u] = 0.0f;
    sh_hB[0][u] = 0.0f;
    __syncthreads();

    // prefetch xp (distance 2) for both samples
    XPre PA0 = ld_xp(xptA, u), PA1 = ld_xp(xptA + G3_, u);
    XPre PB0 = ld_xp(xptB, u), PB1 = ld_xp(xptB + G3_, u);

#pragma unroll 1
    for (int t = 0; t < T_; t++) {
        const int p = t & 1;
        // dual dot products: chains for A and B are independent -> ILP
        unsigned long long arA0 = 0ull, arA1 = 0ull, azA0 = 0ull, azA1 = 0ull,
                           anA0 = 0ull, anA1 = 0ull;
        unsigned long long arB0 = 0ull, arB1 = 0ull, azB0 = 0ull, azB1 = 0ull,
                           anB0 = 0ull, anB1 = 0ull;
        const ulonglong2* h2A = (const ulonglong2*)sh_hA[p];
        const ulonglong2* h2B = (const ulonglong2*)sh_hB[p];
#pragma unroll
        for (int c = 0; c < HID_ / 4; c++) {
            ulonglong2 hvA = h2A[c];
            ulonglong2 hvB = h2B[c];
            FMA2(arA0, hvA.x, wr2[2 * c],     arA0);
            FMA2(arB0, hvB.x, wr2[2 * c],     arB0);
            FMA2(arA1, hvA.y, wr2[2 * c + 1], arA1);
            FMA2(arB1, hvB.y, wr2[2 * c + 1], arB1);
            FMA2(azA0, hvA.x, wz2[2 * c],     azA0);
            FMA2(azB0, hvB.x, wz2[2 * c],     azB0);
            FMA2(azA1, hvA.y, wz2[2 * c + 1], azA1);
            FMA2(azB1, hvB.y, wz2[2 * c + 1], azB1);
            FMA2(anA0, hvA.x, wn2[2 * c],     anA0);
            FMA2(anB0, hvB.x, wn2[2 * c],     anB0);
            FMA2(anA1, hvA.y, wn2[2 * c + 1], anA1);
            FMA2(anB1, hvB.y, wn2[2 * c + 1], anB1);
        }
        unsigned long long srA, szA, snA, srB, szB, snB;
        ADD2(srA, arA0, arA1);
        ADD2(srB, arB0, arB1);
        ADD2(szA, azA0, azA1);
        ADD2(szB, azB0, azB1);
        ADD2(snA, anA0, anA1);
        ADD2(snB, anB0, anB1);

        gru_finish(srA, szA, snA, bhR, bhZ, bhN, PA0, hA);
        gru_finish(srB, szB, snB, bhR, bhZ, bhN, PB0, hB);

        sh_hA[p ^ 1][u] = hA;
        sh_hB[p ^ 1][u] = hB;
        hbA[(size_t)t * HID_ + u] = hA;
        hbB[(size_t)t * HID_ + u] = hB;

        // rotate prefetch registers; fetch t+2
        PA0 = PA1;
        PB0 = PB1;
        int tn = (t + 2 < T_) ? (t + 2) : (T_ - 1);
        PA1 = ld_xp(xptA + (size_t)tn * G3_, u);
        PB1 = ld_xp(xptB + (size_t)tn * G3_, u);

        __syncthreads();
    }
}

// ---------------------------------------------------------------------------
// Kernel 2: per-(n,t) log-likelihood. One thread per (n,t).
// ---------------------------------------------------------------------------
__global__ void __launch_bounds__(256) k_loglik(
    const float* __restrict__ Yi,
    const float* __restrict__ Cw,
    const float* __restrict__ H,
    const float* __restrict__ mu_w,
    const float* __restrict__ W_mu, const float* __restrict__ b_mu,
    const float* __restrict__ W_var, const float* __restrict__ b_var)
{
    __shared__ __align__(16) float sW[HID_ * 2 * NO_]; // [k][2q+s]: s=0 mu, s=1 var
    __shared__ float sH[NO_ * NS_];
    __shared__ float smw[NO_], sbm[NO_], sbv[NO_];
    __shared__ double sred[8];

    const int tid = threadIdx.x;
    for (int i = tid; i < HID_ * 2 * NO_; i += 256) {
        int k = i / (2 * NO_);
        int rr = i - k * 2 * NO_;
        int q = rr >> 1;
        sW[i] = (rr & 1) ? W_var[k * NO_ + q] : W_mu[k * NO_ + q];
    }
    if (tid < NO_ * NS_) sH[tid] = H[tid];
    if (tid < NO_) { smw[tid] = mu_w[tid]; sbm[tid] = b_mu[tid]; sbv[tid] = b_var[tid]; }
    __syncthreads();

    const int gid = blockIdx.x * 256 + tid;   // 0 .. N*T-1
    const int n   = gid / T_;
    const float* hp = g_h + (size_t)gid * HID_;

    float mu[NO_], vr[NO_];
#pragma unroll
    for (int q = 0; q < NO_; q++) { mu[q] = sbm[q]; vr[q] = sbv[q]; }

    const float4* hp4 = (const float4*)hp;
#pragma unroll
    for (int k4 = 0; k4 < HID_ / 4; k4++) {
        float4 hv = hp4[k4];
        float hx[4] = { hv.x, hv.y, hv.z, hv.w };
#pragma unroll
        for (int uu = 0; uu < 4; uu++) {
            const float4* w4 = (const float4*)&sW[(4 * k4 + uu) * 2 * NO_];
#pragma unroll
            for (int q2 = 0; q2 < NO_ / 2; q2++) {
                float4 w = w4[q2];
                mu[2 * q2]     = fmaf(hx[uu], w.x, mu[2 * q2]);
                vr[2 * q2]     = fmaf(hx[uu], w.y, vr[2 * q2]);
                mu[2 * q2 + 1] = fmaf(hx[uu], w.z, mu[2 * q2 + 1]);
                vr[2 * q2 + 1] = fmaf(hx[uu], w.w, vr[2 * q2 + 1]);
            }
        }
    }
    float va[NO_];
#pragma unroll
    for (int q = 0; q < NO_; q++) va[q] = softplusf_(vr[q]);

    // e = y - (H mu + mu_w)
    const float* yp = Yi + (size_t)gid * NO_;
    float ee[NO_];
#pragma unroll
    for (int i = 0; i < NO_; i++) {
        float m = smw[i];
#pragma unroll
        for (int jq = 0; jq < NS_; jq++) m = fmaf(sH[i * NS_ + jq], mu[jq], m);
        ee[i] = yp[i] - m;
    }

    // A (lower) = H diag(va) H^T + Cw_n
    const float* cwp = Cw + (size_t)n * NO_ * NO_;
    float A[55];
#pragma unroll
    for (int i = 0; i < NO_; i++) {
        float hvi[NS_];
#pragma unroll
        for (int jq = 0; jq < NS_; jq++) hvi[jq] = sH[i * NS_ + jq] * va[jq];
#pragma unroll
        for (int k = 0; k <= i; k++) {
            float s = cwp[i * NO_ + k];
#pragma unroll
            for (int jq = 0; jq < NS_; jq++) s = fmaf(hvi[jq], sH[k * NS_ + jq], s);
            A[i * (i + 1) / 2 + k] = s;
        }
    }

    // In-place Cholesky; logdet accumulated as sum log(d^2)
    float dinv[NO_];
    float logdet = 0.0f;
#pragma unroll
    for (int k = 0; k < NO_; k++) {
        float s = A[k * (k + 1) / 2 + k];
#pragma unroll
        for (int jq = 0; jq < k; jq++) {
            float l = A[k * (k + 1) / 2 + jq];
            s = fmaf(-l, l, s);
        }
        logdet += logf(s);
        float d = sqrtf(s);
        float di = 1.0f / d;
        dinv[k] = di;
#pragma unroll
        for (int i = k + 1; i < NO_; i++) {
            float s2 = A[i * (i + 1) / 2 + k];
#pragma unroll
            for (int jq = 0; jq < k; jq++)
                s2 = fmaf(-A[i * (i + 1) / 2 + jq], A[k * (k + 1) / 2 + jq], s2);
            A[i * (i + 1) / 2 + k] = s2 * di;
        }
    }

    // quad = || L^{-1} e ||^2 (forward solve only)
    float quad = 0.0f;
#pragma unroll
    for (int i = 0; i < NO_; i++) {
        float s = ee[i];
#pragma unroll
        for (int jq = 0; jq < i; jq++) s = fmaf(-A[i * (i + 1) / 2 + jq], ee[jq], s);
        s *= dinv[i];
        ee[i] = s;
        quad = fmaf(s, s, quad);
    }

    double local = (double)logdet + (double)quad;
#pragma unroll
    for (int o = 16; o > 0; o >>= 1)
        local += __shfl_down_sync(0xffffffffu, local, o);
    if ((tid & 31) == 0) sred[tid >> 5] = local;
    __syncthreads();
    if (tid == 0) {
        double sum = 0.0;
#pragma unroll
        for (int w = 0; w < 8; w++) sum += sred[w];
        atomicAdd(&g_acc, sum);
    }
}

// ---------------------------------------------------------------------------
// Kernel 3: finalize scalar
// ---------------------------------------------------------------------------
__global__ void k_fin(float* out) {
    out[0] = (float)(-0.91893853320467274178
                     - 0.5 * g_acc / ((double)N_ * (double)T_ * (double)NO_));
}

extern "C" void kernel_launch(void* const* d_in, const int* in_sizes, int n_in,
                              void* d_out, int out_size) {
    const float* Yi    = (const float*)d_in[0];
    const float* Xh    = (const float*)d_in[1];
    const float* Cw    = (const float*)d_in[2];
    const float* H     = (const float*)d_in[3];
    const float* mu_w  = (const float*)d_in[4];
    const float* Wi    = (const float*)d_in[5];
    const float* Wh    = (const float*)d_in[6];
    const float* bi    = (const float*)d_in[7];
    const float* bh    = (const float*)d_in[8];
    const float* W_mu  = (const float*)d_in[9];
    const float* b_mu  = (const float*)d_in[10];
    const float* W_var = (const float*)d_in[11];
    const float* b_var = (const float*)d_in[12];

    k_zero<<<1, 1>>>();
    k_xp<<<(N_ * T_) / 16, G3_>>>(Yi, Xh, Wi, bi);
    k_pad<<<1, 1>>>();   // pad so k_gru sits at launch index 3 (ncu capture slot)
    k_gru<<<N_ / 2, HID_>>>(Wh, bh);
    k_loglik<<<(N_ * T_) / 256, 256>>>(Yi, Cw, H, mu_w, W_mu, b_mu, W_var, b_var);
    k_fin<<<1, 1>>>((float*)d_out);
}

// round 13
// speedup vs baseline: 1.5768x; 1.5768x over previous
#include <cuda_runtime.h>
#include <math.h>

// Problem constants
#define N_   256
#define T_   1000
#define NO_  10
#define NS_  10
#define HID_ 64
#define G3_  192   // 3*HID
#define D_   20    // NO+NS

// Scratch: xproj [N*T,192], hidden states [N,T,64], global double accumulator.
__device__ float  g_xp[(size_t)N_ * T_ * G3_];
__device__ float  g_h[(size_t)N_ * T_ * HID_];
__device__ double g_acc;

__global__ void k_zero() { g_acc = 0.0; }
__global__ void k_pad() { }   // no-op: keeps k_gru at ncu capture slot (idx 3)

// ---- packed f32x2 helpers ----
#define FMA2(d, a, b, c) \
    asm("fma.rn.f32x2 %0, %1, %2, %3;" : "=l"(d) : "l"(a), "l"(b), "l"(c))
#define ADD2(d, a, b) \
    asm("add.rn.f32x2 %0, %1, %2;" : "=l"(d) : "l"(a), "l"(b))
#define PACK2(d, lo, hi) \
    asm("mov.b64 %0, {%1, %2};" : "=l"(d) : "f"(lo), "f"(hi))
#define UNPACK2(lo, hi, s) \
    asm("mov.b64 {%0, %1}, %2;" : "=f"(lo), "=f"(hi) : "l"(s))

// ---- fast activations via MUFU.TANH (sm_75+) ----
__device__ __forceinline__ float tanh_fast(float x) {
    float y;
    asm("tanh.approx.f32 %0, %1;" : "=f"(y) : "f"(x));
    return y;
}
__device__ __forceinline__ float sigmoid_fast(float x) {
    return fmaf(tanh_fast(0.5f * x), 0.5f, 0.5f);
}
__device__ __forceinline__ float softplusf_(float x) {
    float ax = fabsf(x);
    return fmaxf(x, 0.0f) + log1pf(__expf(-ax));
}

// ---------------------------------------------------------------------------
// Kernel 0: precompute input projections xp[nt][192] = concat(y,xhat)@Wi + bi
// ---------------------------------------------------------------------------
__global__ void __launch_bounds__(G3_) k_xp(
    const float* __restrict__ Yi, const float* __restrict__ Xh,
    const float* __restrict__ Wi, const float* __restrict__ bi)
{
    __shared__ float xs[16][D_];
    const int j = threadIdx.x;
    const int nt0 = blockIdx.x * 16;
    for (int i = j; i < 16 * D_; i += G3_) {
        int r = i / D_, d = i - r * D_;
        int nt = nt0 + r;
        xs[r][d] = (d < NO_) ? Yi[(size_t)nt * NO_ + d]
                             : Xh[(size_t)nt * NS_ + (d - NO_)];
    }
    float w[D_];
#pragma unroll
    for (int d = 0; d < D_; d++) w[d] = Wi[d * G3_ + j];
    const float b = bi[j];
    __syncthreads();
#pragma unroll
    for (int r = 0; r < 16; r++) {
        float a = b;
#pragma unroll
        for (int d = 0; d < D_; d++) a = fmaf(xs[r][d], w[d], a);
        g_xp[(size_t)(nt0 + r) * G3_ + j] = a;
    }
}

// ---------------------------------------------------------------------------
// Kernel 1: persistent GRU (R10 structure + register relief).
// One CTA per sample, 64 threads. Thread u owns ALL THREE gates of unit u.
// r/z weights in registers (64 pairs = 128 regs); n-gate weights in SHARED
// (loop-invariant, conflict-free ulonglong2[16][64]) -> ~64 regs freed so
// ptxas can batch the h LDS.128 loads deeply. ONE barrier per step.
// xp+bias folded into accumulator inits. xp prefetch distance 2. MUFU.TANH.
// ---------------------------------------------------------------------------
struct XPre { float r, z, n; };

__device__ __forceinline__ XPre ld_xp(const float* base, int u) {
    XPre o;
    o.r = __ldg(base + u);
    o.z = __ldg(base + HID_ + u);
    o.n = __ldg(base + 2 * HID_ + u);
    return o;
}

__device__ __forceinline__ void gru_step(
    const float* __restrict__ sh_src, float* __restrict__ sh_dst,
    const ulonglong2 (* __restrict__ sWn)[HID_],
    const unsigned long long* wr2, const unsigned long long* wz2,
    float bhR, float bhZ, float bhN,
    XPre xp, float& hreg, float* hb_t, int u)
{
    // fold xp + bias into accumulator inits
    unsigned long long ar0, az0, an0;
    PACK2(ar0, xp.r + bhR, 0.0f);
    PACK2(az0, xp.z + bhZ, 0.0f);
    PACK2(an0, bhN, 0.0f);             // bhN sits inside r*(...)
    unsigned long long ar1 = 0ull, az1 = 0ull, an1 = 0ull;

    const ulonglong2* h2 = (const ulonglong2*)sh_src;
#pragma unroll
    for (int c = 0; c < HID_ / 4; c++) {
        ulonglong2 hv = h2[c];
        ulonglong2 wv = sWn[c][u];     // n-gate weights from shared
        FMA2(ar0, hv.x, wr2[2 * c],     ar0);
        FMA2(ar1, hv.y, wr2[2 * c + 1], ar1);
        FMA2(az0, hv.x, wz2[2 * c],     az0);
        FMA2(az1, hv.y, wz2[2 * c + 1], az1);
        FMA2(an0, hv.x, wv.x, an0);
        FMA2(an1, hv.y, wv.y, an1);
    }
    unsigned long long sr, sz, sn;
    ADD2(sr, ar0, ar1);
    ADD2(sz, az0, az1);
    ADD2(sn, an0, an1);
    float rl, rh, zl, zh, nl, nh;
    UNPACK2(rl, rh, sr);
    UNPACK2(zl, zh, sz);
    UNPACK2(nl, nh, sn);
    float r  = sigmoid_fast(rl + rh);
    float z  = sigmoid_fast(zl + zh);
    float nn = tanh_fast(xp.n + r * (nl + nh));
    hreg = fmaf(z, hreg - nn, nn);       // (1-z)*nn + z*h
    sh_dst[u] = hreg;
    hb_t[u] = hreg;
    __syncthreads();
}

__global__ void __launch_bounds__(HID_, 2) k_gru(
    const float* __restrict__ Wh, const float* __restrict__ bh)
{
    __shared__ __align__(16) float sh_h[2][HID_];
    __shared__ __align__(16) ulonglong2 sWn[HID_ / 4][HID_];  // 16KB, n-gate

    const int u = threadIdx.x;     // unit id, 0..63
    const int n = blockIdx.x;

    // r/z weights in registers: 64 packed pairs
    unsigned long long wr2[HID_ / 2], wz2[HID_ / 2];
#pragma unroll
    for (int k = 0; k < HID_ / 2; k++) {
        float a, b;
        a = Wh[(2 * k) * G3_ + u];             b = Wh[(2 * k + 1) * G3_ + u];
        PACK2(wr2[k], a, b);
        a = Wh[(2 * k) * G3_ + HID_ + u];      b = Wh[(2 * k + 1) * G3_ + HID_ + u];
        PACK2(wz2[k], a, b);
    }
    // n-gate weights into shared (each thread fills its own column)
#pragma unroll
    for (int c = 0; c < HID_ / 4; c++) {
        float a = Wh[(4 * c)     * G3_ + 2 * HID_ + u];
        float b = Wh[(4 * c + 1) * G3_ + 2 * HID_ + u];
        float e = Wh[(4 * c + 2) * G3_ + 2 * HID_ + u];
        float f = Wh[(4 * c + 3) * G3_ + 2 * HID_ + u];
        unsigned long long lo, hi;
        PACK2(lo, a, b);
        PACK2(hi, e, f);
        sWn[c][u] = make_ulonglong2(lo, hi);
    }
    const float bhR = bh[u], bhZ = bh[HID_ + u], bhN = bh[2 * HID_ + u];

    const float* xpt = g_xp + (size_t)n * T_ * G3_;
    float*       hb  = g_h  + (size_t)n * T_ * HID_;

    float hreg = 0.0f;
    sh_h[0][u] = 0.0f;
    __syncthreads();

    // prefetch xp for t=0 and t=1
    XPre P0 = ld_xp(xpt, u);
    XPre P1 = ld_xp(xpt + G3_, u);

#pragma unroll 1
    for (int t = 0; t < T_; t += 2) {
        // step t (even): src buf 0, dst buf 1
        gru_step(sh_h[0], sh_h[1], sWn, wr2, wz2, bhR, bhZ, bhN,
                 P0, hreg, hb + (size_t)t * HID_, u);
        {   // prefetch t+2 (clamped)
            int tn = (t + 2 < T_) ? (t + 2) : (T_ - 1);
            P0 = ld_xp(xpt + (size_t)tn * G3_, u);
        }
        // step t+1 (odd): src buf 1, dst buf 0
        gru_step(sh_h[1], sh_h[0], sWn, wr2, wz2, bhR, bhZ, bhN,
                 P1, hreg, hb + (size_t)(t + 1) * HID_, u);
        {   // prefetch t+3
            int tn = (t + 3 < T_) ? (t + 3) : (T_ - 1);
            P1 = ld_xp(xpt + (size_t)tn * G3_, u);
        }
    }
}

// ---------------------------------------------------------------------------
// Kernel 2: per-(n,t) log-likelihood. One thread per (n,t).
// ---------------------------------------------------------------------------
__global__ void __launch_bounds__(256) k_loglik(
    const float* __restrict__ Yi,
    const float* __restrict__ Cw,
    const float* __restrict__ H,
    const float* __restrict__ mu_w,
    const float* __restrict__ W_mu, const float* __restrict__ b_mu,
    const float* __restrict__ W_var, const float* __restrict__ b_var)
{
    __shared__ __align__(16) float sW[HID_ * 2 * NO_]; // [k][2q+s]: s=0 mu, s=1 var
    __shared__ float sH[NO_ * NS_];
    __shared__ float smw[NO_], sbm[NO_], sbv[NO_];
    __shared__ double sred[8];

    const int tid = threadIdx.x;
    for (int i = tid; i < HID_ * 2 * NO_; i += 256) {
        int k = i / (2 * NO_);
        int rr = i - k * 2 * NO_;
        int q = rr >> 1;
        sW[i] = (rr & 1) ? W_var[k * NO_ + q] : W_mu[k * NO_ + q];
    }
    if (tid < NO_ * NS_) sH[tid] = H[tid];
    if (tid < NO_) { smw[tid] = mu_w[tid]; sbm[tid] = b_mu[tid]; sbv[tid] = b_var[tid]; }
    __syncthreads();

    const int gid = blockIdx.x * 256 + tid;   // 0 .. N*T-1
    const int n   = gid / T_;
    const float* hp = g_h + (size_t)gid * HID_;

    float mu[NO_], vr[NO_];
#pragma unroll
    for (int q = 0; q < NO_; q++) { mu[q] = sbm[q]; vr[q] = sbv[q]; }

    const float4* hp4 = (const float4*)hp;
#pragma unroll
    for (int k4 = 0; k4 < HID_ / 4; k4++) {
        float4 hv = hp4[k4];
        float hx[4] = { hv.x, hv.y, hv.z, hv.w };
#pragma unroll
        for (int uu = 0; uu < 4; uu++) {
            const float4* w4 = (const float4*)&sW[(4 * k4 + uu) * 2 * NO_];
#pragma unroll
            for (int q2 = 0; q2 < NO_ / 2; q2++) {
                float4 w = w4[q2];
                mu[2 * q2]     = fmaf(hx[uu], w.x, mu[2 * q2]);
                vr[2 * q2]     = fmaf(hx[uu], w.y, vr[2 * q2]);
                mu[2 * q2 + 1] = fmaf(hx[uu], w.z, mu[2 * q2 + 1]);
                vr[2 * q2 + 1] = fmaf(hx[uu], w.w, vr[2 * q2 + 1]);
            }
        }
    }
    float va[NO_];
#pragma unroll
    for (int q = 0; q < NO_; q++) va[q] = softplusf_(vr[q]);

    // e = y - (H mu + mu_w)
    const float* yp = Yi + (size_t)gid * NO_;
    float ee[NO_];
#pragma unroll
    for (int i = 0; i < NO_; i++) {
        float m = smw[i];
#pragma unroll
        for (int jq = 0; jq < NS_; jq++) m = fmaf(sH[i * NS_ + jq], mu[jq], m);
        ee[i] = yp[i] - m;
    }

    // A (lower) = H diag(va) H^T + Cw_n
    const float* cwp = Cw + (size_t)n * NO_ * NO_;
    float A[55];
#pragma unroll
    for (int i = 0; i < NO_; i++) {
        float hvi[NS_];
#pragma unroll
        for (int jq = 0; jq < NS_; jq++) hvi[jq] = sH[i * NS_ + jq] * va[jq];
#pragma unroll
        for (int k = 0; k <= i; k++) {
            float s = cwp[i * NO_ + k];
#pragma unroll
            for (int jq = 0; jq < NS_; jq++) s = fmaf(hvi[jq], sH[k * NS_ + jq], s);
            A[i * (i + 1) / 2 + k] = s;
        }
    }

    // In-place Cholesky; logdet accumulated as sum log(d^2)
    float dinv[NO_];
    float logdet = 0.0f;
#pragma unroll
    for (int k = 0; k < NO_; k++) {
        float s = A[k * (k + 1) / 2 + k];
#pragma unroll
        for (int jq = 0; jq < k; jq++) {
            float l = A[k * (k + 1) / 2 + jq];
            s = fmaf(-l, l, s);
        }
        logdet += logf(s);
        float d = sqrtf(s);
        float di = 1.0f / d;
        dinv[k] = di;
#pragma unroll
        for (int i = k + 1; i < NO_; i++) {
            float s2 = A[i * (i + 1) / 2 + k];
#pragma unroll
            for (int jq = 0; jq < k; jq++)
                s2 = fmaf(-A[i * (i + 1) / 2 + jq], A[k * (k + 1) / 2 + jq], s2);
            A[i * (i + 1) / 2 + k] = s2 * di;
        }
    }

    // quad = || L^{-1} e ||^2 (forward solve only)
    float quad = 0.0f;
#pragma unroll
    for (int i = 0; i < NO_; i++) {
        float s = ee[i];
#pragma unroll
        for (int jq = 0; jq < i; jq++) s = fmaf(-A[i * (i + 1) / 2 + jq], ee[jq], s);
        s *= dinv[i];
        ee[i] = s;
        quad = fmaf(s, s, quad);
    }

    double local = (double)logdet + (double)quad;
#pragma unroll
    for (int o = 16; o > 0; o >>= 1)
        local += __shfl_down_sync(0xffffffffu, local, o);
    if ((tid & 31) == 0) sred[tid >> 5] = local;
    __syncthreads();
    if (tid == 0) {
        double sum = 0.0;
#pragma unroll
        for (int w = 0; w < 8; w++) sum += sred[w];
        atomicAdd(&g_acc, sum);
    }
}

// ---------------------------------------------------------------------------
// Kernel 3: finalize scalar
// ---------------------------------------------------------------------------
__global__ void k_fin(float* out) {
    out[0] = (float)(-0.91893853320467274178
                     - 0.5 * g_acc / ((double)N_ * (double)T_ * (double)NO_));
}

extern "C" void kernel_launch(void* const* d_in, const int* in_sizes, int n_in,
                              void* d_out, int out_size) {
    const float* Yi    = (const float*)d_in[0];
    const float* Xh    = (const float*)d_in[1];
    const float* Cw    = (const float*)d_in[2];
    const float* H     = (const float*)d_in[3];
    const float* mu_w  = (const float*)d_in[4];
    const float* Wi    = (const float*)d_in[5];
    const float* Wh    = (const float*)d_in[6];
    const float* bi    = (const float*)d_in[7];
    const float* bh    = (const float*)d_in[8];
    const float* W_mu  = (const float*)d_in[9];
    const float* b_mu  = (const float*)d_in[10];
    const float* W_var = (const float*)d_in[11];
    const float* b_var = (const float*)d_in[12];

    k_zero<<<1, 1>>>();
    k_xp<<<(N_ * T_) / 16, G3_>>>(Yi, Xh, Wi, bi);
    k_pad<<<1, 1>>>();   // pad so k_gru sits at launch index 3 (ncu capture slot)
    k_gru<<<N_, HID_>>>(Wh, bh);
    k_loglik<<<(N_ * T_) / 256, 256>>>(Yi, Cw, H, mu_w, W_mu, b_mu, W_var, b_var);
    k_fin<<<1, 1>>>((float*)d_out);
}

// round 14
// speedup vs baseline: 2.1626x; 1.3715x over previous
#include <cuda_runtime.h>
#include <math.h>

// Problem constants
#define N_   256
#define T_   1000
#define NO_  10
#define NS_  10
#define HID_ 64
#define G3_  192   // 3*HID
#define D_   20    // NO+NS

// Scratch: hidden states [N,T,64] and global double accumulator.
__device__ float  g_h[(size_t)N_ * T_ * HID_];
__device__ double g_acc;

__global__ void k_zero() { g_acc = 0.0; }
__global__ void k_pad() { }   // no-op: keeps k_gru at ncu capture slot (idx 3)

// ---- packed f32x2 helpers ----
#define FMA2(d, a, b, c) \
    asm("fma.rn.f32x2 %0, %1, %2, %3;" : "=l"(d) : "l"(a), "l"(b), "l"(c))
#define ADD2(d, a, b) \
    asm("add.rn.f32x2 %0, %1, %2;" : "=l"(d) : "l"(a), "l"(b))
#define PACK2(d, lo, hi) \
    asm("mov.b64 %0, {%1, %2};" : "=l"(d) : "f"(lo), "f"(hi))
#define UNPACK2(lo, hi, s) \
    asm("mov.b64 {%0, %1}, %2;" : "=f"(lo), "=f"(hi) : "l"(s))

// ---- fast activations via MUFU.TANH (sm_75+) ----
__device__ __forceinline__ float tanh_fast(float x) {
    float y;
    asm("tanh.approx.f32 %0, %1;" : "=f"(y) : "f"(x));
    return y;
}
__device__ __forceinline__ float sigmoid_fast(float x) {
    return fmaf(tanh_fast(0.5f * x), 0.5f, 0.5f);
}
__device__ __forceinline__ float softplusf_(float x) {
    float ax = fabsf(x);
    return fmaxf(x, 0.0f) + log1pf(__expf(-ax));
}

// ---------------------------------------------------------------------------
// Kernel 1: persistent fused GRU. One CTA per sample, 128 threads.
//   warps 0,1 (tid 0-63)   : CONSUMERS — exact R10 recurrence core
//                            (2 CTAs/SM -> 2 warps on each of SMSP0/1)
//   warps 2,3 (tid 64-127) : PRODUCERS — compute xp[t+2] = x@Wi+bi into a
//                            4-stage shared ring on the otherwise-idle SMSP2/3
// ONE __syncthreads per step separates ring stage (t) reads from (t+2) writes.
// ---------------------------------------------------------------------------
__device__ __forceinline__ void ld_raw(float2* X, const float* yb,
                                       const float* xb, int t) {
    const float2* y2 = (const float2*)(yb + (size_t)t * NO_);
    const float2* x2 = (const float2*)(xb + (size_t)t * NS_);
#pragma unroll
    for (int i = 0; i < 5; i++) X[i]     = __ldg(y2 + i);
#pragma unroll
    for (int i = 0; i < 5; i++) X[5 + i] = __ldg(x2 + i);
}

__device__ __forceinline__ void produce(
    float* __restrict__ dst, const float2* X,
    const float* w0, const float* w1, const float* w2,
    float b0, float b1, float b2, int p)
{
    float a0 = b0, a1 = b1, a2 = b2;
#pragma unroll
    for (int i = 0; i < 10; i++) {      // d = 2i, 2i+1 ascending (matches ref)
        a0 = fmaf(X[i].x, w0[2 * i], a0);
        a0 = fmaf(X[i].y, w0[2 * i + 1], a0);
        a1 = fmaf(X[i].x, w1[2 * i], a1);
        a1 = fmaf(X[i].y, w1[2 * i + 1], a1);
        a2 = fmaf(X[i].x, w2[2 * i], a2);
        a2 = fmaf(X[i].y, w2[2 * i + 1], a2);
    }
    dst[p]            = a0;
    dst[HID_ + p]     = a1;
    dst[2 * HID_ + p] = a2;
}

__global__ void __launch_bounds__(128, 2) k_gru(
    const float* __restrict__ Yi, const float* __restrict__ Xh,
    const float* __restrict__ Wi, const float* __restrict__ bi,
    const float* __restrict__ Wh, const float* __restrict__ bh)
{
    __shared__ __align__(16) float sh_h[2][HID_];
    __shared__ __align__(16) float ring[4][G3_];

    const int tid = threadIdx.x;
    const int n   = blockIdx.x;

    if (tid < HID_) {
        // ======================= CONSUMER (R10 core) =======================
        const int u = tid;
        unsigned long long wr2[HID_ / 2], wz2[HID_ / 2], wn2[HID_ / 2];
#pragma unroll
        for (int k = 0; k < HID_ / 2; k++) {
            float a, b;
            a = Wh[(2 * k) * G3_ + u];             b = Wh[(2 * k + 1) * G3_ + u];
            PACK2(wr2[k], a, b);
            a = Wh[(2 * k) * G3_ + HID_ + u];      b = Wh[(2 * k + 1) * G3_ + HID_ + u];
            PACK2(wz2[k], a, b);
            a = Wh[(2 * k) * G3_ + 2 * HID_ + u];  b = Wh[(2 * k + 1) * G3_ + 2 * HID_ + u];
            PACK2(wn2[k], a, b);
        }
        const float bhR = bh[u], bhZ = bh[HID_ + u], bhN = bh[2 * HID_ + u];
        float* hb = g_h + (size_t)n * T_ * HID_;

        float hreg = 0.0f;
        sh_h[0][u] = 0.0f;
        __syncthreads();                           // sync #0 (ring 0,1 ready)

#pragma unroll 1
        for (int t = 0; t < T_; t++) {
            const int p = t & 1;
            const float* rg = ring[t & 3];
            float xr = rg[u];
            float xz = rg[HID_ + u];
            float xn = rg[2 * HID_ + u];

            unsigned long long ar0 = 0ull, ar1 = 0ull;
            unsigned long long az0 = 0ull, az1 = 0ull;
            unsigned long long an0 = 0ull, an1 = 0ull;
            const ulonglong2* h2 = (const ulonglong2*)sh_h[p];
#pragma unroll
            for (int c = 0; c < HID_ / 4; c++) {
                ulonglong2 hv = h2[c];
                FMA2(ar0, hv.x, wr2[2 * c],     ar0);
                FMA2(ar1, hv.y, wr2[2 * c + 1], ar1);
                FMA2(az0, hv.x, wz2[2 * c],     az0);
                FMA2(az1, hv.y, wz2[2 * c + 1], az1);
                FMA2(an0, hv.x, wn2[2 * c],     an0);
                FMA2(an1, hv.y, wn2[2 * c + 1], an1);
            }
            unsigned long long sr, sz, sn;
            ADD2(sr, ar0, ar1);
            ADD2(sz, az0, az1);
            ADD2(sn, an0, an1);
            float rl, rh, zl, zh, nl, nh;
            UNPACK2(rl, rh, sr);
            UNPACK2(zl, zh, sz);
            UNPACK2(nl, nh, sn);
            float r  = sigmoid_fast(xr + bhR + rl + rh);
            float z  = sigmoid_fast(xz + bhZ + zl + zh);
            float nn = tanh_fast(xn + r * (bhN + nl + nh));
            hreg = fmaf(z, hreg - nn, nn);         // (1-z)*nn + z*h

            sh_h[p ^ 1][u] = hreg;
            hb[(size_t)t * HID_ + u] = hreg;
            __syncthreads();
        }
    } else {
        // ========================== PRODUCER ==========================
        const int p = tid - HID_;                  // 0..63
        float wi0[D_], wi1[D_], wi2[D_];
#pragma unroll
        for (int d = 0; d < D_; d++) {
            wi0[d] = Wi[d * G3_ + p];
            wi1[d] = Wi[d * G3_ + HID_ + p];
            wi2[d] = Wi[d * G3_ + 2 * HID_ + p];
        }
        const float b0 = bi[p], b1 = bi[HID_ + p], b2 = bi[2 * HID_ + p];
        const float* yb = Yi + (size_t)n * T_ * NO_;
        const float* xb = Xh + (size_t)n * T_ * NS_;

        float2 R0[10], R1[10];
        // prologue: fill ring stages 0 and 1; prefetch raw t=2,3
        ld_raw(R0, yb, xb, 0);
        ld_raw(R1, yb, xb, 1);
        produce(ring[0], R0, wi0, wi1, wi2, b0, b1, b2, p);
        produce(ring[1], R1, wi0, wi1, wi2, b0, b1, b2, p);
        ld_raw(R0, yb, xb, 2);
        ld_raw(R1, yb, xb, 3);
        __syncthreads();                           // sync #0

#pragma unroll 1
        for (int t = 0; t < T_; t += 2) {
            // step t: produce xp[t+2] from R0; prefetch raw t+4
            produce(ring[(t + 2) & 3], R0, wi0, wi1, wi2, b0, b1, b2, p);
            {
                int tn = (t + 4 < T_) ? (t + 4) : (T_ - 1);
                ld_raw(R0, yb, xb, tn);
            }
            __syncthreads();
            // step t+1: produce xp[t+3] from R1; prefetch raw t+5
            produce(ring[(t + 3) & 3], R1, wi0, wi1, wi2, b0, b1, b2, p);
            {
                int tn = (t + 5 < T_) ? (t + 5) : (T_ - 1);
                ld_raw(R1, yb, xb, tn);
            }
            __syncthreads();
        }
    }
}

// ---------------------------------------------------------------------------
// Kernel 2: per-(n,t) log-likelihood. One thread per (n,t).
// ---------------------------------------------------------------------------
__global__ void __launch_bounds__(256) k_loglik(
    const float* __restrict__ Yi,
    const float* __restrict__ Cw,
    const float* __restrict__ H,
    const float* __restrict__ mu_w,
    const float* __restrict__ W_mu, const float* __restrict__ b_mu,
    const float* __restrict__ W_var, const float* __restrict__ b_var)
{
    __shared__ __align__(16) float sW[HID_ * 2 * NO_]; // [k][2q+s]: s=0 mu, s=1 var
    __shared__ float sH[NO_ * NS_];
    __shared__ float smw[NO_], sbm[NO_], sbv[NO_];
    __shared__ double sred[8];

    const int tid = threadIdx.x;
    for (int i = tid; i < HID_ * 2 * NO_; i += 256) {
        int k = i / (2 * NO_);
        int rr = i - k * 2 * NO_;
        int q = rr >> 1;
        sW[i] = (rr & 1) ? W_var[k * NO_ + q] : W_mu[k * NO_ + q];
    }
    if (tid < NO_ * NS_) sH[tid] = H[tid];
    if (tid < NO_) { smw[tid] = mu_w[tid]; sbm[tid] = b_mu[tid]; sbv[tid] = b_var[tid]; }
    __syncthreads();

    const int gid = blockIdx.x * 256 + tid;   // 0 .. N*T-1
    const int n   = gid / T_;
    const float* hp = g_h + (size_t)gid * HID_;

    float mu[NO_], vr[NO_];
#pragma unroll
    for (int q = 0; q < NO_; q++) { mu[q] = sbm[q]; vr[q] = sbv[q]; }

    const float4* hp4 = (const float4*)hp;
#pragma unroll
    for (int k4 = 0; k4 < HID_ / 4; k4++) {
        float4 hv = hp4[k4];
        float hx[4] = { hv.x, hv.y, hv.z, hv.w };
#pragma unroll
        for (int uu = 0; uu < 4; uu++) {
            const float4* w4 = (const float4*)&sW[(4 * k4 + uu) * 2 * NO_];
#pragma unroll
            for (int q2 = 0; q2 < NO_ / 2; q2++) {
                float4 w = w4[q2];
                mu[2 * q2]     = fmaf(hx[uu], w.x, mu[2 * q2]);
                vr[2 * q2]     = fmaf(hx[uu], w.y, vr[2 * q2]);
                mu[2 * q2 + 1] = fmaf(hx[uu], w.z, mu[2 * q2 + 1]);
                vr[2 * q2 + 1] = fmaf(hx[uu], w.w, vr[2 * q2 + 1]);
            }
        }
    }
    float va[NO_];
#pragma unroll
    for (int q = 0; q < NO_; q++) va[q] = softplusf_(vr[q]);

    // e = y - (H mu + mu_w)
    const float* yp = Yi + (size_t)gid * NO_;
    float ee[NO_];
#pragma unroll
    for (int i = 0; i < NO_; i++) {
        float m = smw[i];
#pragma unroll
        for (int jq = 0; jq < NS_; jq++) m = fmaf(sH[i * NS_ + jq], mu[jq], m);
        ee[i] = yp[i] - m;
    }

    // A (lower) = H diag(va) H^T + Cw_n
    const float* cwp = Cw + (size_t)n * NO_ * NO_;
    float A[55];
#pragma unroll
    for (int i = 0; i < NO_; i++) {
        float hvi[NS_];
#pragma unroll
        for (int jq = 0; jq < NS_; jq++) hvi[jq] = sH[i * NS_ + jq] * va[jq];
#pragma unroll
        for (int k = 0; k <= i; k++) {
            float s = cwp[i * NO_ + k];
#pragma unroll
            for (int jq = 0; jq < NS_; jq++) s = fmaf(hvi[jq], sH[k * NS_ + jq], s);
            A[i * (i + 1) / 2 + k] = s;
        }
    }

    // In-place Cholesky; logdet accumulated as sum log(d^2)
    float dinv[NO_];
    float logdet = 0.0f;
#pragma unroll
    for (int k = 0; k < NO_; k++) {
        float s = A[k * (k + 1) / 2 + k];
#pragma unroll
        for (int jq = 0; jq < k; jq++) {
            float l = A[k * (k + 1) / 2 + jq];
            s = fmaf(-l, l, s);
        }
        logdet += logf(s);
        float d = sqrtf(s);
        float di = 1.0f / d;
        dinv[k] = di;
#pragma unroll
        for (int i = k + 1; i < NO_; i++) {
            float s2 = A[i * (i + 1) / 2 + k];
#pragma unroll
            for (int jq = 0; jq < k; jq++)
                s2 = fmaf(-A[i * (i + 1) / 2 + jq], A[k * (k + 1) / 2 + jq], s2);
            A[i * (i + 1) / 2 + k] = s2 * di;
        }
    }

    // quad = || L^{-1} e ||^2 (forward solve only)
    float quad = 0.0f;
#pragma unroll
    for (int i = 0; i < NO_; i++) {
        float s = ee[i];
#pragma unroll
        for (int jq = 0; jq < i; jq++) s = fmaf(-A[i * (i + 1) / 2 + jq], ee[jq], s);
        s *= dinv[i];
        ee[i] = s;
        quad = fmaf(s, s, quad);
    }

    double local = (double)logdet + (double)quad;
#pragma unroll
    for (int o = 16; o > 0; o >>= 1)
        local += __shfl_down_sync(0xffffffffu, local, o);
    if ((tid & 31) == 0) sred[tid >> 5] = local;
    __syncthreads();
    if (tid == 0) {
        double sum = 0.0;
#pragma unroll
        for (int w = 0; w < 8; w++) sum += sred[w];
        atomicAdd(&g_acc, sum);
    }
}

// ---------------------------------------------------------------------------
// Kernel 3: finalize scalar
// ---------------------------------------------------------------------------
__global__ void k_fin(float* out) {
    out[0] = (float)(-0.91893853320467274178
                     - 0.5 * g_acc / ((double)N_ * (double)T_ * (double)NO_));
}

extern "C" void kernel_launch(void* const* d_in, const int* in_sizes, int n_in,
                              void* d_out, int out_size) {
    const float* Yi    = (const float*)d_in[0];
    const float* Xh    = (const float*)d_in[1];
    const float* Cw    = (const float*)d_in[2];
    const float* H     = (const float*)d_in[3];
    const float* mu_w  = (const float*)d_in[4];
    const float* Wi    = (const float*)d_in[5];
    const float* Wh    = (const float*)d_in[6];
    const float* bi    = (const float*)d_in[7];
    const float* bh    = (const float*)d_in[8];
    const float* W_mu  = (const float*)d_in[9];
    const float* b_mu  = (const float*)d_in[10];
    const float* W_var = (const float*)d_in[11];
    const float* b_var = (const float*)d_in[12];

    k_zero<<<1, 1>>>();
    k_pad<<<1, 1>>>();
    k_pad<<<1, 1>>>();   // keep k_gru at launch index 3 (ncu capture slot)
    k_gru<<<N_, 128>>>(Yi, Xh, Wi, bi, Wh, bh);
    k_loglik<<<(N_ * T_) / 256, 256>>>(Yi, Cw, H, mu_w, W_mu, b_mu, W_var, b_var);
    k_fin<<<1, 1>>>((float*)d_out);
}

// round 16
// speedup vs baseline: 2.7307x; 1.2627x over previous
#include <cuda_runtime.h>
#include <math.h>

// Problem constants
#define N_   256
#define T_   1000
#define NO_  10
#define NS_  10
#define HID_ 64
#define G3_  192   // 3*HID
#define D_   20    // NO+NS

// Scratch: hidden states [N,T,64] and global double accumulator.
__device__ float  g_h[(size_t)N_ * T_ * HID_];
__device__ double g_acc;

__global__ void k_zero() { g_acc = 0.0; }
__global__ void k_pad() { }   // no-op: keeps k_gru at ncu capture slot (idx 3)

// ---- packed f32x2 helpers ----
#define FMA2(d, a, b, c) \
    asm("fma.rn.f32x2 %0, %1, %2, %3;" : "=l"(d) : "l"(a), "l"(b), "l"(c))
#define ADD2(d, a, b) \
    asm("add.rn.f32x2 %0, %1, %2;" : "=l"(d) : "l"(a), "l"(b))
#define PACK2(d, lo, hi) \
    asm("mov.b64 %0, {%1, %2};" : "=l"(d) : "f"(lo), "f"(hi))
#define UNPACK2(lo, hi, s) \
    asm("mov.b64 {%0, %1}, %2;" : "=f"(lo), "=f"(hi) : "l"(s))

// ---- fast activations via MUFU.TANH (sm_75+) ----
__device__ __forceinline__ float tanh_fast(float x) {
    float y;
    asm("tanh.approx.f32 %0, %1;" : "=f"(y) : "f"(x));
    return y;
}
__device__ __forceinline__ float sigmoid_fast(float x) {
    return fmaf(tanh_fast(0.5f * x), 0.5f, 0.5f);
}
__device__ __forceinline__ float softplusf_(float x) {
    float ax = fabsf(x);
    return fmaxf(x, 0.0f) + log1pf(__expf(-ax));
}

// ---------------------------------------------------------------------------
// Kernel 1: persistent fused GRU. TWO samples per CTA, 256 threads, grid 128
// (one CTA per SM). Warp -> SMSP pairing puts ONE consumer + ONE producer on
// every SMSP (decorrelated stalls):
//   warps 0..3 : CONSUMERS  (w>>1 = sample slot, w&1 = unit half)
//   warps 4..7 : PRODUCERS  ((w-4)>>1 = sample slot, (w-4)&1 = column half)
// Consumers run the recurrence (96 FMA2 + h LDS per step); producers compute
// xp[t+2] = x@Wi+bi into a per-sample 4-stage ring. ONE barrier per step.
// ---------------------------------------------------------------------------
__device__ __forceinline__ void ld_raw(float2* X, const float* yb,
                                       const float* xb, int t) {
    const float2* y2 = (const float2*)(yb + (size_t)t * NO_);
    const float2* x2 = (const float2*)(xb + (size_t)t * NS_);
#pragma unroll
    for (int i = 0; i < 5; i++) X[i]     = __ldg(y2 + i);
#pragma unroll
    for (int i = 0; i < 5; i++) X[5 + i] = __ldg(x2 + i);
}

__device__ __forceinline__ void produce(
    float* __restrict__ dst, const float2* X,
    const float* w0, const float* w1, const float* w2,
    float b0, float b1, float b2, int p)
{
    float a0 = b0, a1 = b1, a2 = b2;
#pragma unroll
    for (int i = 0; i < 10; i++) {      // d = 2i, 2i+1 ascending (matches ref)
        a0 = fmaf(X[i].x, w0[2 * i], a0);
        a0 = fmaf(X[i].y, w0[2 * i + 1], a0);
        a1 = fmaf(X[i].x, w1[2 * i], a1);
        a1 = fmaf(X[i].y, w1[2 * i + 1], a1);
        a2 = fmaf(X[i].x, w2[2 * i], a2);
        a2 = fmaf(X[i].y, w2[2 * i + 1], a2);
    }
    dst[p]            = a0;
    dst[HID_ + p]     = a1;
    dst[2 * HID_ + p] = a2;
}

__global__ void __launch_bounds__(256, 1) k_gru(
    const float* __restrict__ Yi, const float* __restrict__ Xh,
    const float* __restrict__ Wi, const float* __restrict__ bi,
    const float* __restrict__ Wh, const float* __restrict__ bh)
{
    __shared__ __align__(16) float sh_h[2][2][HID_];   // [sample][buf][unit]
    __shared__ __align__(16) float ring[2][4][G3_];    // [sample][stage][col]

    const int tid  = threadIdx.x;
    const int w    = tid >> 5;
    const int lane = tid & 31;

    if (w < 4) {
        // ======================= CONSUMER =======================
        const int s = w >> 1;                    // sample slot
        const int u = ((w & 1) << 5) + lane;     // unit id 0..63
        const int n = blockIdx.x * 2 + s;

        unsigned long long wr2[HID_ / 2], wz2[HID_ / 2], wn2[HID_ / 2];
#pragma unroll
        for (int k = 0; k < HID_ / 2; k++) {
            float a, b;
            a = Wh[(2 * k) * G3_ + u];             b = Wh[(2 * k + 1) * G3_ + u];
            PACK2(wr2[k], a, b);
            a = Wh[(2 * k) * G3_ + HID_ + u];      b = Wh[(2 * k + 1) * G3_ + HID_ + u];
            PACK2(wz2[k], a, b);
            a = Wh[(2 * k) * G3_ + 2 * HID_ + u];  b = Wh[(2 * k + 1) * G3_ + 2 * HID_ + u];
            PACK2(wn2[k], a, b);
        }
        const float bhR = bh[u], bhZ = bh[HID_ + u], bhN = bh[2 * HID_ + u];
        float* hb = g_h + (size_t)n * T_ * HID_;

        float hreg = 0.0f;
        sh_h[s][0][u] = 0.0f;
        __syncthreads();                           // sync #0 (ring 0,1 ready)

#pragma unroll 1
        for (int t = 0; t < T_; t++) {
            const int p = t & 1;
            const float* rg = ring[s][t & 3];
            float xr = rg[u];
            float xz = rg[HID_ + u];
            float xn = rg[2 * HID_ + u];

            unsigned long long ar0 = 0ull, ar1 = 0ull;
            unsigned long long az0 = 0ull, az1 = 0ull;
            unsigned long long an0 = 0ull, an1 = 0ull;
            const ulonglong2* h2 = (const ulonglong2*)sh_h[s][p];
#pragma unroll
            for (int c = 0; c < HID_ / 4; c++) {
                ulonglong2 hv = h2[c];
                FMA2(ar0, hv.x, wr2[2 * c],     ar0);
                FMA2(ar1, hv.y, wr2[2 * c + 1], ar1);
                FMA2(az0, hv.x, wz2[2 * c],     az0);
                FMA2(az1, hv.y, wz2[2 * c + 1], az1);
                FMA2(an0, hv.x, wn2[2 * c],     an0);
                FMA2(an1, hv.y, wn2[2 * c + 1], an1);
            }
            unsigned long long sr, sz, sn;
            ADD2(sr, ar0, ar1);
            ADD2(sz, az0, az1);
            ADD2(sn, an0, an1);
            float rl, rh, zl, zh, nl, nh;
            UNPACK2(rl, rh, sr);
            UNPACK2(zl, zh, sz);
            UNPACK2(nl, nh, sn);
            float r  = sigmoid_fast(xr + bhR + rl + rh);
            float z  = sigmoid_fast(xz + bhZ + zl + zh);
            float nn = tanh_fast(xn + r * (bhN + nl + nh));
            hreg = fmaf(z, hreg - nn, nn);         // (1-z)*nn + z*h

            sh_h[s][p ^ 1][u] = hreg;
            hb[(size_t)t * HID_ + u] = hreg;
            __syncthreads();
        }
    } else {
        // ========================== PRODUCER ==========================
        const int w2 = w - 4;
        const int s  = w2 >> 1;                   // sample slot
        const int p  = ((w2 & 1) << 5) + lane;    // column 0..63
        const int n  = blockIdx.x * 2 + s;

        float wi0[D_], wi1[D_], wi2[D_];
#pragma unroll
        for (int d = 0; d < D_; d++) {
            wi0[d] = Wi[d * G3_ + p];
            wi1[d] = Wi[d * G3_ + HID_ + p];
            wi2[d] = Wi[d * G3_ + 2 * HID_ + p];
        }
        const float b0 = bi[p], b1 = bi[HID_ + p], b2 = bi[2 * HID_ + p];
        const float* yb = Yi + (size_t)n * T_ * NO_;
        const float* xb = Xh + (size_t)n * T_ * NS_;

        float2 R0[10], R1[10];
        // prologue: fill ring stages 0 and 1; prefetch raw t=2,3
        ld_raw(R0, yb, xb, 0);
        ld_raw(R1, yb, xb, 1);
        produce(ring[s][0], R0, wi0, wi1, wi2, b0, b1, b2, p);
        produce(ring[s][1], R1, wi0, wi1, wi2, b0, b1, b2, p);
        ld_raw(R0, yb, xb, 2);
        ld_raw(R1, yb, xb, 3);
        __syncthreads();                           // sync #0

#pragma unroll 1
        for (int t = 0; t < T_; t += 2) {
            // step t: produce xp[t+2] from R0; prefetch raw t+4
            produce(ring[s][(t + 2) & 3], R0, wi0, wi1, wi2, b0, b1, b2, p);
            {
                int tn = (t + 4 < T_) ? (t + 4) : (T_ - 1);
                ld_raw(R0, yb, xb, tn);
            }
            __syncthreads();
            // step t+1: produce xp[t+3] from R1; prefetch raw t+5
            produce(ring[s][(t + 3) & 3], R1, wi0, wi1, wi2, b0, b1, b2, p);
            {
                int tn = (t + 5 < T_) ? (t + 5) : (T_ - 1);
                ld_raw(R1, yb, xb, tn);
            }
            __syncthreads();
        }
    }
}

// ---------------------------------------------------------------------------
// Kernel 2: per-(n,t) log-likelihood. One thread per (n,t).
// ---------------------------------------------------------------------------
__global__ void __launch_bounds__(256) k_loglik(
    const float* __restrict__ Yi,
    const float* __restrict__ Cw,
    const float* __restrict__ H,
    const float* __restrict__ mu_w,
    const float* __restrict__ W_mu, const float* __restrict__ b_mu,
    const float* __restrict__ W_var, const float* __restrict__ b_var)
{
    __shared__ __align__(16) float sW[HID_ * 2 * NO_]; // [k][2q+s]: s=0 mu, s=1 var
    __shared__ float sH[NO_ * NS_];
    __shared__ float smw[NO_], sbm[NO_], sbv[NO_];
    __shared__ double sred[8];

    const int tid = threadIdx.x;
    for (int i = tid; i < HID_ * 2 * NO_; i += 256) {
        int k = i / (2 * NO_);
        int rr = i - k * 2 * NO_;
        int q = rr >> 1;
        sW[i] = (rr & 1) ? W_var[k * NO_ + q] : W_mu[k * NO_ + q];
    }
    if (tid < NO_ * NS_) sH[tid] = H[tid];
    if (tid < NO_) { smw[tid] = mu_w[tid]; sbm[tid] = b_mu[tid]; sbv[tid] = b_var[tid]; }
    __syncthreads();

    const int gid = blockIdx.x * 256 + tid;   // 0 .. N*T-1
    const int n   = gid / T_;
    const float* hp = g_h + (size_t)gid * HID_;

    float mu[NO_], vr[NO_];
#pragma unroll
    for (int q = 0; q < NO_; q++) { mu[q] = sbm[q]; vr[q] = sbv[q]; }

    const float4* hp4 = (const float4*)hp;
#pragma unroll
    for (int k4 = 0; k4 < HID_ / 4; k4++) {
        float4 hv = hp4[k4];
        float hx[4] = { hv.x, hv.y, hv.z, hv.w };
#pragma unroll
        for (int uu = 0; uu < 4; uu++) {
            const float4* w4 = (const float4*)&sW[(4 * k4 + uu) * 2 * NO_];
#pragma unroll
            for (int q2 = 0; q2 < NO_ / 2; q2++) {
                float4 ww = w4[q2];
                mu[2 * q2]     = fmaf(hx[uu], ww.x, mu[2 * q2]);
                vr[2 * q2]     = fmaf(hx[uu], ww.y, vr[2 * q2]);
                mu[2 * q2 + 1] = fmaf(hx[uu], ww.z, mu[2 * q2 + 1]);
                vr[2 * q2 + 1] = fmaf(hx[uu], ww.w, vr[2 * q2 + 1]);
            }
        }
    }
    float va[NO_];
#pragma unroll
    for (int q = 0; q < NO_; q++) va[q] = softplusf_(vr[q]);

    // e = y - (H mu + mu_w)
    const float* yp = Yi + (size_t)gid * NO_;
    float ee[NO_];
#pragma unroll
    for (int i = 0; i < NO_; i++) {
        float m = smw[i];
#pragma unroll
        for (int jq = 0; jq < NS_; jq++) m = fmaf(sH[i * NS_ + jq], mu[jq], m);
        ee[i] = yp[i] - m;
    }

    // A (lower) = H diag(va) H^T + Cw_n
    const float* cwp = Cw + (size_t)n * NO_ * NO_;
    float A[55];
#pragma unroll
    for (int i = 0; i < NO_; i++) {
        float hvi[NS_];
#pragma unroll
        for (int jq = 0; jq < NS_; jq++) hvi[jq] = sH[i * NS_ + jq] * va[jq];
#pragma unroll
        for (int k = 0; k <= i; k++) {
            float s = cwp[i * NO_ + k];
#pragma unroll
            for (int jq = 0; jq < NS_; jq++) s = fmaf(hvi[jq], sH[k * NS_ + jq], s);
            A[i * (i + 1) / 2 + k] = s;
        }
    }

    // In-place Cholesky; logdet accumulated as sum log(d^2)
    float dinv[NO_];
    float logdet = 0.0f;
#pragma unroll
    for (int k = 0; k < NO_; k++) {
        float s = A[k * (k + 1) / 2 + k];
#pragma unroll
        for (int jq = 0; jq < k; jq++) {
            float l = A[k * (k + 1) / 2 + jq];
            s = fmaf(-l, l, s);
        }
        logdet += logf(s);
        float d = sqrtf(s);
        float di = 1.0f / d;
        dinv[k] = di;
#pragma unroll
        for (int i = k + 1; i < NO_; i++) {
            float s2 = A[i * (i + 1) / 2 + k];
#pragma unroll
            for (int jq = 0; jq < k; jq++)
                s2 = fmaf(-A[i * (i + 1) / 2 + jq], A[k * (k + 1) / 2 + jq], s2);
            A[i * (i + 1) / 2 + k] = s2 * di;
        }
    }

    // quad = || L^{-1} e ||^2 (forward solve only)
    float quad = 0.0f;
#pragma unroll
    for (int i = 0; i < NO_; i++) {
        float s = ee[i];
#pragma unroll
        for (int jq = 0; jq < i; jq++) s = fmaf(-A[i * (i + 1) / 2 + jq], ee[jq], s);
        s *= dinv[i];
        ee[i] = s;
        quad = fmaf(s, s, quad);
    }

    double local = (double)logdet + (double)quad;
#pragma unroll
    for (int o = 16; o > 0; o >>= 1)
        local += __shfl_down_sync(0xffffffffu, local, o);
    if ((tid & 31) == 0) sred[tid >> 5] = local;
    __syncthreads();
    if (tid == 0) {
        double sum = 0.0;
#pragma unroll
        for (int w2 = 0; w2 < 8; w2++) sum += sred[w2];
        atomicAdd(&g_acc, sum);
    }
}

// ---------------------------------------------------------------------------
// Kernel 3: finalize scalar
// ---------------------------------------------------------------------------
__global__ void k_fin(float* out) {
    out[0] = (float)(-0.91893853320467274178
                     - 0.5 * g_acc / ((double)N_ * (double)T_ * (double)NO_));
}

extern "C" void kernel_launch(void* const* d_in, const int* in_sizes, int n_in,
                              void* d_out, int out_size) {
    const float* Yi    = (const float*)d_in[0];
    const float* Xh    = (const float*)d_in[1];
    const float* Cw    = (const float*)d_in[2];
    const float* H     = (const float*)d_in[3];
    const float* mu_w  = (const float*)d_in[4];
    const float* Wi    = (const float*)d_in[5];
    const float* Wh    = (const float*)d_in[6];
    const float* bi    = (const float*)d_in[7];
    const float* bh    = (const float*)d_in[8];
    const float* W_mu  = (const float*)d_in[9];
    const float* b_mu  = (const float*)d_in[10];
    const float* W_var = (const float*)d_in[11];
    const float* b_var = (const float*)d_in[12];

    k_zero<<<1, 1>>>();
    k_pad<<<1, 1>>>();
    k_pad<<<1, 1>>>();   // keep k_gru at launch index 3 (ncu capture slot)
    k_gru<<<N_ / 2, 256>>>(Yi, Xh, Wi, bi, Wh, bh);
    k_loglik<<<(N_ * T_) / 256, 256>>>(Yi, Cw, H, mu_w, W_mu, b_mu, W_var, b_var);
    k_fin<<<1, 1>>>((float*)d_out);
}

// round 17
// speedup vs baseline: 2.7989x; 1.0250x over previous
#include <cuda_runtime.h>
#include <math.h>

// Problem constants
#define N_   256
#define T_   1000
#define NO_  10
#define NS_  10
#define HID_ 64
#define G3_  192   // 3*HID
#define D_   20    // NO+NS

// Scratch: hidden states [N,T,64] and global double accumulator.
__device__ float  g_h[(size_t)N_ * T_ * HID_];
__device__ double g_acc;

__global__ void k_zero() { g_acc = 0.0; }
__global__ void k_pad() { }   // no-op: keeps k_gru at ncu capture slot (idx 3)

// ---- packed f32x2 helpers ----
#define FMA2(d, a, b, c) \
    asm("fma.rn.f32x2 %0, %1, %2, %3;" : "=l"(d) : "l"(a), "l"(b), "l"(c))
#define ADD2(d, a, b) \
    asm("add.rn.f32x2 %0, %1, %2;" : "=l"(d) : "l"(a), "l"(b))
#define PACK2(d, lo, hi) \
    asm("mov.b64 %0, {%1, %2};" : "=l"(d) : "f"(lo), "f"(hi))
#define UNPACK2(lo, hi, s) \
    asm("mov.b64 {%0, %1}, %2;" : "=f"(lo), "=f"(hi) : "l"(s))

// per-sample named barrier: 4 warps (128 threads) of one sample slot
#define SAMPLE_BAR(s) \
    asm volatile("bar.sync %0, %1;" :: "r"((s) + 1), "r"(128) : "memory")

// ---- fast activations via MUFU.TANH (sm_75+) ----
__device__ __forceinline__ float tanh_fast(float x) {
    float y;
    asm("tanh.approx.f32 %0, %1;" : "=f"(y) : "f"(x));
    return y;
}
__device__ __forceinline__ float sigmoid_fast(float x) {
    return fmaf(tanh_fast(0.5f * x), 0.5f, 0.5f);
}
__device__ __forceinline__ float softplusf_(float x) {
    float ax = fabsf(x);
    return fmaxf(x, 0.0f) + log1pf(__expf(-ax));
}

// ---------------------------------------------------------------------------
// Kernel 1: persistent fused GRU. TWO samples per CTA, 256 threads, grid 128.
//   warps 0..3 : CONSUMERS  (w>>1 = sample slot, w&1 = unit half)
//   warps 4..7 : PRODUCERS  ((w-4)>>1 = sample slot, (w-4)&1 = column half)
// Sample s occupies SMSPs {2s, 2s+1} with one consumer + one producer warp
// each. Per-sample NAMED barriers (bar.sync s+1, 128) decouple the samples.
// Producers compute xp[t+2] = x@Wi+bi (packed f32x2) into a 4-stage ring.
// ---------------------------------------------------------------------------
__device__ __forceinline__ void ld_raw(float2* X, const float* yb,
                                       const float* xb, int t) {
    const float2* y2 = (const float2*)(yb + (size_t)t * NO_);
    const float2* x2 = (const float2*)(xb + (size_t)t * NS_);
#pragma unroll
    for (int i = 0; i < 5; i++) X[i]     = __ldg(y2 + i);
#pragma unroll
    for (int i = 0; i < 5; i++) X[5 + i] = __ldg(x2 + i);
}

// packed producer: 3 gate columns x 10 FMA2
__device__ __forceinline__ void produce(
    float* __restrict__ dst, const float2* X,
    const unsigned long long* w0, const unsigned long long* w1,
    const unsigned long long* w2,
    float b0, float b1, float b2, int p)
{
    unsigned long long a0 = 0ull, a1 = 0ull, a2 = 0ull;
#pragma unroll
    for (int i = 0; i < 10; i++) {
        unsigned long long xv;
        PACK2(xv, X[i].x, X[i].y);
        FMA2(a0, xv, w0[i], a0);
        FMA2(a1, xv, w1[i], a1);
        FMA2(a2, xv, w2[i], a2);
    }
    float l0, h0, l1, h1, l2, h2;
    UNPACK2(l0, h0, a0);
    UNPACK2(l1, h1, a1);
    UNPACK2(l2, h2, a2);
    dst[p]            = b0 + l0 + h0;
    dst[HID_ + p]     = b1 + l1 + h1;
    dst[2 * HID_ + p] = b2 + l2 + h2;
}

__global__ void __launch_bounds__(256, 1) k_gru(
    const float* __restrict__ Yi, const float* __restrict__ Xh,
    const float* __restrict__ Wi, const float* __restrict__ bi,
    const float* __restrict__ Wh, const float* __restrict__ bh)
{
    __shared__ __align__(16) float sh_h[2][2][HID_];   // [sample][buf][unit]
    __shared__ __align__(16) float ring[2][4][G3_];    // [sample][stage][col]

    const int tid  = threadIdx.x;
    const int w    = tid >> 5;
    const int lane = tid & 31;

    if (w < 4) {
        // ======================= CONSUMER =======================
        const int s = w >> 1;                    // sample slot
        const int u = ((w & 1) << 5) + lane;     // unit id 0..63
        const int n = blockIdx.x * 2 + s;

        unsigned long long wr2[HID_ / 2], wz2[HID_ / 2], wn2[HID_ / 2];
#pragma unroll
        for (int k = 0; k < HID_ / 2; k++) {
            float a, b;
            a = Wh[(2 * k) * G3_ + u];             b = Wh[(2 * k + 1) * G3_ + u];
            PACK2(wr2[k], a, b);
            a = Wh[(2 * k) * G3_ + HID_ + u];      b = Wh[(2 * k + 1) * G3_ + HID_ + u];
            PACK2(wz2[k], a, b);
            a = Wh[(2 * k) * G3_ + 2 * HID_ + u];  b = Wh[(2 * k + 1) * G3_ + 2 * HID_ + u];
            PACK2(wn2[k], a, b);
        }
        const float bhR = bh[u], bhZ = bh[HID_ + u], bhN = bh[2 * HID_ + u];
        float* hb = g_h + (size_t)n * T_ * HID_;

        float hreg = 0.0f;
        sh_h[s][0][u] = 0.0f;
        SAMPLE_BAR(s);                             // sync #0 (ring 0,1 ready)

#pragma unroll 1
        for (int t = 0; t < T_; t++) {
            const int p = t & 1;
            const float* rg = ring[s][t & 3];
            float xr = rg[u];
            float xz = rg[HID_ + u];
            float xn = rg[2 * HID_ + u];

            unsigned long long ar0 = 0ull, ar1 = 0ull;
            unsigned long long az0 = 0ull, az1 = 0ull;
            unsigned long long an0 = 0ull, an1 = 0ull;
            const ulonglong2* h2 = (const ulonglong2*)sh_h[s][p];
#pragma unroll
            for (int c = 0; c < HID_ / 4; c++) {
                ulonglong2 hv = h2[c];
                FMA2(ar0, hv.x, wr2[2 * c],     ar0);
                FMA2(ar1, hv.y, wr2[2 * c + 1], ar1);
                FMA2(az0, hv.x, wz2[2 * c],     az0);
                FMA2(az1, hv.y, wz2[2 * c + 1], az1);
                FMA2(an0, hv.x, wn2[2 * c],     an0);
                FMA2(an1, hv.y, wn2[2 * c + 1], an1);
            }
            unsigned long long sr, sz, sn;
            ADD2(sr, ar0, ar1);
            ADD2(sz, az0, az1);
            ADD2(sn, an0, an1);
            float rl, rh, zl, zh, nl, nh;
            UNPACK2(rl, rh, sr);
            UNPACK2(zl, zh, sz);
            UNPACK2(nl, nh, sn);
            float r  = sigmoid_fast(xr + bhR + rl + rh);
            float z  = sigmoid_fast(xz + bhZ + zl + zh);
            float nn = tanh_fast(xn + r * (bhN + nl + nh));
            hreg = fmaf(z, hreg - nn, nn);         // (1-z)*nn + z*h

            sh_h[s][p ^ 1][u] = hreg;
            hb[(size_t)t * HID_ + u] = hreg;
            SAMPLE_BAR(s);
        }
    } else {
        // ========================== PRODUCER ==========================
        const int w2 = w - 4;
        const int s  = w2 >> 1;                   // sample slot
        const int p  = ((w2 & 1) << 5) + lane;    // column 0..63
        const int n  = blockIdx.x * 2 + s;

        unsigned long long wi0[10], wi1[10], wi2[10];
#pragma unroll
        for (int i = 0; i < 10; i++) {
            float a, b;
            a = Wi[(2 * i) * G3_ + p];
            b = Wi[(2 * i + 1) * G3_ + p];
            PACK2(wi0[i], a, b);
            a = Wi[(2 * i) * G3_ + HID_ + p];
            b = Wi[(2 * i + 1) * G3_ + HID_ + p];
            PACK2(wi1[i], a, b);
            a = Wi[(2 * i) * G3_ + 2 * HID_ + p];
            b = Wi[(2 * i + 1) * G3_ + 2 * HID_ + p];
            PACK2(wi2[i], a, b);
        }
        const float b0 = bi[p], b1 = bi[HID_ + p], b2 = bi[2 * HID_ + p];
        const float* yb = Yi + (size_t)n * T_ * NO_;
        const float* xb = Xh + (size_t)n * T_ * NS_;

        float2 R0[10], R1[10];
        // prologue: fill ring stages 0 and 1; prefetch raw t=2,3
        ld_raw(R0, yb, xb, 0);
        ld_raw(R1, yb, xb, 1);
        produce(ring[s][0], R0, wi0, wi1, wi2, b0, b1, b2, p);
        produce(ring[s][1], R1, wi0, wi1, wi2, b0, b1, b2, p);
        ld_raw(R0, yb, xb, 2);
        ld_raw(R1, yb, xb, 3);
        SAMPLE_BAR(s);                             // sync #0

#pragma unroll 1
        for (int t = 0; t < T_; t += 2) {
            // step t: produce xp[t+2] from R0; prefetch raw t+4
            produce(ring[s][(t + 2) & 3], R0, wi0, wi1, wi2, b0, b1, b2, p);
            {
                int tn = (t + 4 < T_) ? (t + 4) : (T_ - 1);
                ld_raw(R0, yb, xb, tn);
            }
            SAMPLE_BAR(s);
            // step t+1: produce xp[t+3] from R1; prefetch raw t+5
            produce(ring[s][(t + 3) & 3], R1, wi0, wi1, wi2, b0, b1, b2, p);
            {
                int tn = (t + 5 < T_) ? (t + 5) : (T_ - 1);
                ld_raw(R1, yb, xb, tn);
            }
            SAMPLE_BAR(s);
        }
    }
}

// ---------------------------------------------------------------------------
// Kernel 2: per-(n,t) log-likelihood. One thread per (n,t).
// ---------------------------------------------------------------------------
__global__ void __launch_bounds__(256) k_loglik(
    const float* __restrict__ Yi,
    const float* __restrict__ Cw,
    const float* __restrict__ H,
    const float* __restrict__ mu_w,
    const float* __restrict__ W_mu, const float* __restrict__ b_mu,
    const float* __restrict__ W_var, const float* __restrict__ b_var)
{
    __shared__ __align__(16) float sW[HID_ * 2 * NO_]; // [k][2q+s]: s=0 mu, s=1 var
    __shared__ float sH[NO_ * NS_];
    __shared__ float smw[NO_], sbm[NO_], sbv[NO_];
    __shared__ double sred[8];

    const int tid = threadIdx.x;
    for (int i = tid; i < HID_ * 2 * NO_; i += 256) {
        int k = i / (2 * NO_);
        int rr = i - k * 2 * NO_;
        int q = rr >> 1;
        sW[i] = (rr & 1) ? W_var[k * NO_ + q] : W_mu[k * NO_ + q];
    }
    if (tid < NO_ * NS_) sH[tid] = H[tid];
    if (tid < NO_) { smw[tid] = mu_w[tid]; sbm[tid] = b_mu[tid]; sbv[tid] = b_var[tid]; }
    __syncthreads();

    const int gid = blockIdx.x * 256 + tid;   // 0 .. N*T-1
    const int n   = gid / T_;
    const float* hp = g_h + (size_t)gid * HID_;

    float mu[NO_], vr[NO_];
#pragma unroll
    for (int q = 0; q < NO_; q++) { mu[q] = sbm[q]; vr[q] = sbv[q]; }

    const float4* hp4 = (const float4*)hp;
#pragma unroll
    for (int k4 = 0; k4 < HID_ / 4; k4++) {
        float4 hv = hp4[k4];
        float hx[4] = { hv.x, hv.y, hv.z, hv.w };
#pragma unroll
        for (int uu = 0; uu < 4; uu++) {
            const float4* w4 = (const float4*)&sW[(4 * k4 + uu) * 2 * NO_];
#pragma unroll
            for (int q2 = 0; q2 < NO_ / 2; q2++) {
                float4 ww = w4[q2];
                mu[2 * q2]     = fmaf(hx[uu], ww.x, mu[2 * q2]);
                vr[2 * q2]     = fmaf(hx[uu], ww.y, vr[2 * q2]);
                mu[2 * q2 + 1] = fmaf(hx[uu], ww.z, mu[2 * q2 + 1]);
                vr[2 * q2 + 1] = fmaf(hx[uu], ww.w, vr[2 * q2 + 1]);
            }
        }
    }
    float va[NO_];
#pragma unroll
    for (int q = 0; q < NO_; q++) va[q] = softplusf_(vr[q]);

    // e = y - (H mu + mu_w)
    const float* yp = Yi + (size_t)gid * NO_;
    float ee[NO_];
#pragma unroll
    for (int i = 0; i < NO_; i++) {
        float m = smw[i];
#pragma unroll
        for (int jq = 0; jq < NS_; jq++) m = fmaf(sH[i * NS_ + jq], mu[jq], m);
        ee[i] = yp[i] - m;
    }

    // A (lower) = H diag(va) H^T + Cw_n
    const float* cwp = Cw + (size_t)n * NO_ * NO_;
    float A[55];
#pragma unroll
    for (int i = 0; i < NO_; i++) {
        float hvi[NS_];
#pragma unroll
        for (int jq = 0; jq < NS_; jq++) hvi[jq] = sH[i * NS_ + jq] * va[jq];
#pragma unroll
        for (int k = 0; k <= i; k++) {
            float s = cwp[i * NO_ + k];
#pragma unroll
            for (int jq = 0; jq < NS_; jq++) s = fmaf(hvi[jq], sH[k * NS_ + jq], s);
            A[i * (i + 1) / 2 + k] = s;
        }
    }

    // In-place Cholesky; logdet accumulated as sum log(d^2)
    float dinv[NO_];
    float logdet = 0.0f;
#pragma unroll
    for (int k = 0; k < NO_; k++) {
        float s = A[k * (k + 1) / 2 + k];
#pragma unroll
        for (int jq = 0; jq < k; jq++) {
            float l = A[k * (k + 1) / 2 + jq];
            s = fmaf(-l, l, s);
        }
        logdet += logf(s);
        float d = sqrtf(s);
        float di = 1.0f / d;
        dinv[k] = di;
#pragma unroll
        for (int i = k + 1; i < NO_; i++) {
            float s2 = A[i * (i + 1) / 2 + k];
#pragma unroll
            for (int jq = 0; jq < k; jq++)
                s2 = fmaf(-A[i * (i + 1) / 2 + jq], A[k * (k + 1) / 2 + jq], s2);
            A[i * (i + 1) / 2 + k] = s2 * di;
        }
    }

    // quad = || L^{-1} e ||^2 (forward solve only)
    float quad = 0.0f;
#pragma unroll
    for (int i = 0; i < NO_; i++) {
        float s = ee[i];
#pragma unroll
        for (int jq = 0; jq < i; jq++) s = fmaf(-A[i * (i + 1) / 2 + jq], ee[jq], s);
        s *= dinv[i];
        ee[i] = s;
        quad = fmaf(s, s, quad);
    }

    double local = (double)logdet + (double)quad;
#pragma unroll
    for (int o = 16; o > 0; o >>= 1)
        local += __shfl_down_sync(0xffffffffu, local, o);
    if ((tid & 31) == 0) sred[tid >> 5] = local;
    __syncthreads();
    if (tid == 0) {
        double sum = 0.0;
#pragma unroll
        for (int w2 = 0; w2 < 8; w2++) sum += sred[w2];
        atomicAdd(&g_acc, sum);
    }
}

// ---------------------------------------------------------------------------
// Kernel 3: finalize scalar
// ---------------------------------------------------------------------------
__global__ void k_fin(float* out) {
    out[0] = (float)(-0.91893853320467274178
                     - 0.5 * g_acc / ((double)N_ * (double)T_ * (double)NO_));
}

extern "C" void kernel_launch(void* const* d_in, const int* in_sizes, int n_in,
                              void* d_out, int out_size) {
    const float* Yi    = (const float*)d_in[0];
    const float* Xh    = (const float*)d_in[1];
    const float* Cw    = (const float*)d_in[2];
    const float* H     = (const float*)d_in[3];
    const float* mu_w  = (const float*)d_in[4];
    const float* Wi    = (const float*)d_in[5];
    const float* Wh    = (const float*)d_in[6];
    const float* bi    = (const float*)d_in[7];
    const float* bh    = (const float*)d_in[8];
    const float* W_mu  = (const float*)d_in[9];
    const float* b_mu  = (const float*)d_in[10];
    const float* W_var = (const float*)d_in[11];
    const float* b_var = (const float*)d_in[12];

    k_zero<<<1, 1>>>();
    k_pad<<<1, 1>>>();
    k_pad<<<1, 1>>>();   // keep k_gru at launch index 3 (ncu capture slot)
    k_gru<<<N_ / 2, 256>>>(Yi, Xh, Wi, bi, Wh, bh);
    k_loglik<<<(N_ * T_) / 256, 256>>>(Yi, Cw, H, mu_w, W_mu, b_mu, W_var, b_var);
    k_fin<<<1, 1>>>((float*)d_out);
}